// round 3
// baseline (speedup 1.0000x reference)
#include <cuda_runtime.h>
#include <math.h>

#define HW 16384
#define BB 4
#define KK 20

// ---------------- scratch (device globals; no runtime allocation) ----------
__device__ float g_t1[4ll*256*128*128];   // conv1 raw output (pre-GN)  64 MB
__device__ float g_t2[4ll*128*128*128];   // conv2 raw output           32 MB
__device__ float g_t3[4ll*64*128*128];    // conv3 raw output           16 MB
__device__ float g_stats1[2*4*8];         // (mean, rstd) per (b, group)
__device__ float g_stats2[2*4*4];
__device__ float g_stats3[2*4*4];
__device__ float g_sums[4*20*64];
__device__ float g_cnts[4*20];

// ---------------- zero accumulators ----------------------------------------
__global__ void zero_kernel() {
    int tid = threadIdx.x;
    for (int i = tid; i < 4*20*64; i += 256) g_sums[i] = 0.f;
    if (tid < 80) g_cnts[tid] = 0.f;
}

// ---------------- direct 3x3 conv, SAME padding, optional GN+ReLU on load --
// Block: 256 threads (16x16). Spatial tile 32x32 (2x2 micro per thread,
// micro offsets dy in {0,1}, dx in {0,16} for conflict-light LDS).
// 16 output channels per block. Input channels staged 4 at a time in smem.
template<int IC, int OC, int GROUPS_IN>
__global__ __launch_bounds__(256, 2)
void conv3x3_kernel(const float* __restrict__ in,
                    const float* __restrict__ wgt,    // [OC][IC][3][3]
                    const float* __restrict__ bias,   // [OC]
                    const float* __restrict__ stats,  // [B*GROUPS_IN][2]
                    const float* __restrict__ gnw,
                    const float* __restrict__ gnb,
                    float* __restrict__ out)
{
    constexpr int ICC = 4;
    __shared__ float s_in[ICC][34][34];
    __shared__ float s_w[16][ICC][9];

    const int tid = threadIdx.x;
    const int tx = tid & 15, ty = tid >> 4;
    const int tileY = blockIdx.x >> 2, tileX = blockIdx.x & 3;
    const int ocBase = blockIdx.y * 16;
    const int b = blockIdx.z;
    const int gy0 = tileY * 32, gx0 = tileX * 32;

    float acc[16][2][2];
#pragma unroll
    for (int o = 0; o < 16; o++)
#pragma unroll
        for (int r = 0; r < 2; r++)
#pragma unroll
            for (int s = 0; s < 2; s++) acc[o][r][s] = 0.f;

#pragma unroll 1
    for (int ic0 = 0; ic0 < IC; ic0 += ICC) {
        // stage input tile (with halo); apply GN+ReLU of previous layer here
        for (int idx = tid; idx < ICC * 34 * 34; idx += 256) {
            int ic  = idx / (34 * 34);
            int rem = idx - ic * (34 * 34);
            int yy  = rem / 34, xx = rem - yy * 34;
            int gy  = gy0 + yy - 1, gx = gx0 + xx - 1;
            float v = 0.f;
            int c = ic0 + ic;
            if (gy >= 0 && gy < 128 && gx >= 0 && gx < 128) {
                v = in[(((size_t)b * IC + c) * HW) + gy * 128 + gx];
                if constexpr (GROUPS_IN > 0) {
                    int g   = c / (IC / GROUPS_IN);
                    float m  = stats[(b * GROUPS_IN + g) * 2];
                    float rs = stats[(b * GROUPS_IN + g) * 2 + 1];
                    v = fmaxf(0.f, (v - m) * rs * gnw[c] + gnb[c]);
                }
            }
            s_in[ic][yy][xx] = v;
        }
        // stage weights
        for (int idx = tid; idx < 16 * ICC * 9; idx += 256) {
            int oc  = idx / (ICC * 9);
            int rem = idx - oc * (ICC * 9);
            int ic  = rem / 9, k = rem - ic * 9;
            s_w[oc][ic][k] = wgt[((size_t)(ocBase + oc) * IC + ic0 + ic) * 9 + k];
        }
        __syncthreads();

#pragma unroll 1
        for (int ic = 0; ic < ICC; ic++) {
            float rin[4][2][3];
#pragma unroll
            for (int rr = 0; rr < 4; rr++)
#pragma unroll
                for (int s = 0; s < 2; s++)
#pragma unroll
                    for (int cc = 0; cc < 3; cc++)
                        rin[rr][s][cc] = s_in[ic][2 * ty + rr][tx + 16 * s + cc];
#pragma unroll
            for (int ky = 0; ky < 3; ky++)
#pragma unroll
                for (int kx = 0; kx < 3; kx++)
#pragma unroll
                    for (int o = 0; o < 16; o++) {
                        float wv = s_w[o][ic][ky * 3 + kx];
#pragma unroll
                        for (int r = 0; r < 2; r++)
#pragma unroll
                            for (int s = 0; s < 2; s++)
                                acc[o][r][s] = fmaf(rin[ky + r][s][kx], wv, acc[o][r][s]);
                    }
        }
        __syncthreads();
    }

#pragma unroll
    for (int o = 0; o < 16; o++) {
        int c = ocBase + o;
        float bv = bias[c];
#pragma unroll
        for (int r = 0; r < 2; r++)
#pragma unroll
            for (int s = 0; s < 2; s++) {
                int gy = gy0 + 2 * ty + r, gx = gx0 + tx + 16 * s;
                out[((size_t)b * OC + c) * HW + gy * 128 + gx] = acc[o][r][s] + bv;
            }
    }
}

// ---------------- per-(b,group) mean/rstd ----------------------------------
template<int C, int G>
__global__ void gn_stats_kernel(const float* __restrict__ t, float* __restrict__ stats)
{
    constexpr int Cg = C / G;
    const int bg = blockIdx.x;                 // = b*G + g; slab is contiguous
    const size_t n = (size_t)Cg * HW;
    const float4* p = (const float4*)(t + (size_t)bg * n);
    const size_t n4 = n / 4;
    float s = 0.f, s2 = 0.f;
    for (size_t i = threadIdx.x; i < n4; i += blockDim.x) {
        float4 v = p[i];
        s  += v.x + v.y + v.z + v.w;
        s2 += v.x * v.x + v.y * v.y + v.z * v.z + v.w * v.w;
    }
    __shared__ float sh[2][8];
    for (int off = 16; off; off >>= 1) {
        s  += __shfl_down_sync(0xffffffffu, s,  off);
        s2 += __shfl_down_sync(0xffffffffu, s2, off);
    }
    int w = threadIdx.x >> 5, l = threadIdx.x & 31;
    if (l == 0) { sh[0][w] = s; sh[1][w] = s2; }
    __syncthreads();
    if (threadIdx.x == 0) {
        float S = 0.f, S2 = 0.f;
        for (int i = 0; i < 8; i++) { S += sh[0][i]; S2 += sh[1][i]; }
        float mean = S / (float)n;
        float var  = S2 / (float)n - mean * mean;
        stats[bg * 2]     = mean;
        stats[bg * 2 + 1] = rsqrtf(var + 1e-5f);
    }
}

// ---------------- masked segment-sum pooling (GN3+ReLU applied inline) -----
__global__ void pool_kernel(const int* __restrict__ masks,
                            const float* __restrict__ g3w,
                            const float* __restrict__ g3b)
{
    __shared__ float s_sum[20][64];
    __shared__ float s_cnt[20];
    const int tid = threadIdx.x;
    const int b = blockIdx.y;
    const int base = blockIdx.x * 1024;

    for (int i = tid; i < 20 * 64; i += 256) ((float*)s_sum)[i] = 0.f;
    if (tid < 20) s_cnt[tid] = 0.f;
    __syncthreads();

    const int* mp = masks + b * HW + base;
    for (int c = 0; c < 64; c++) {
        const int g = c >> 4;                       // 64 ch / 4 groups = 16
        const float m  = g_stats3[(b * 4 + g) * 2];
        const float rs = g_stats3[(b * 4 + g) * 2 + 1];
        const float gw = g3w[c], gb = g3b[c];
        const float* tp = g_t3 + ((size_t)b * 64 + c) * HW + base;
        for (int p = tid; p < 1024; p += 256) {
            int id = mp[p];
            if (id > 0) {
                float v = fmaxf(0.f, (tp[p] - m) * rs * gw + gb);
                atomicAdd(&s_sum[id - 1][c], v);
                if (c == 0) atomicAdd(&s_cnt[id - 1], 1.f);
            }
        }
    }
    __syncthreads();
    for (int i = tid; i < 20 * 64; i += 256) {
        int k = i >> 6, c = i & 63;
        atomicAdd(&g_sums[((size_t)b * 20 + k) * 64 + c], s_sum[k][c]);
    }
    if (tid < 20) atomicAdd(&g_cnts[b * 20 + tid], s_cnt[tid]);
}

// ---------------- heads: boxes [4,20,7] then scores [4,20] -----------------
__global__ void head_kernel(const float* __restrict__ wb, const float* __restrict__ bb,
                            const float* __restrict__ wc, const float* __restrict__ bc,
                            float* __restrict__ out)
{
    int t = threadIdx.x;
    if (t >= 640) return;
    int b = t / 160;
    int rem = t - b * 160;
    int k = rem >> 3, o = rem & 7;
    float inv = 1.f / (g_cnts[b * 20 + k] + 1e-6f);
    const float* sp = &g_sums[((size_t)b * 20 + k) * 64];
    if (o < 7) {
        float s = bb[o];
        for (int c = 0; c < 64; c++) s += sp[c] * inv * wb[o * 64 + c];
        out[(b * 20 + k) * 7 + o] = s;
    } else {
        float s = bc[0];
        for (int c = 0; c < 64; c++) s += sp[c] * inv * wc[c];
        out[560 + b * 20 + k] = 1.f / (1.f + expf(-s));
    }
}

// ---------------- launch ----------------------------------------------------
extern "C" void kernel_launch(void* const* d_in, const int* in_sizes, int n_in,
                              void* d_out, int out_size)
{
    const float* x   = (const float*)d_in[0];
    const int*   mk  = (const int*)  d_in[1];
    const float* w1  = (const float*)d_in[2];
    const float* b1  = (const float*)d_in[3];
    const float* g1w = (const float*)d_in[4];
    const float* g1b = (const float*)d_in[5];
    const float* w2  = (const float*)d_in[6];
    const float* b2  = (const float*)d_in[7];
    const float* g2w = (const float*)d_in[8];
    const float* g2b = (const float*)d_in[9];
    const float* w3  = (const float*)d_in[10];
    const float* b3  = (const float*)d_in[11];
    const float* g3w = (const float*)d_in[12];
    const float* g3b = (const float*)d_in[13];
    const float* wb  = (const float*)d_in[14];
    const float* bb  = (const float*)d_in[15];
    const float* wc  = (const float*)d_in[16];
    const float* bc  = (const float*)d_in[17];
    float* out = (float*)d_out;

    float *t1, *t2, *t3, *st1, *st2, *st3;
    cudaGetSymbolAddress((void**)&t1,  g_t1);
    cudaGetSymbolAddress((void**)&t2,  g_t2);
    cudaGetSymbolAddress((void**)&t3,  g_t3);
    cudaGetSymbolAddress((void**)&st1, g_stats1);
    cudaGetSymbolAddress((void**)&st2, g_stats2);
    cudaGetSymbolAddress((void**)&st3, g_stats3);

    zero_kernel<<<1, 256>>>();

    // conv1: x[4,512,128,128] -> t1[4,256,...]
    conv3x3_kernel<512, 256, 0><<<dim3(16, 16, 4), 256>>>(
        x, w1, b1, nullptr, nullptr, nullptr, t1);
    gn_stats_kernel<256, 8><<<32, 256>>>(t1, st1);

    // conv2: GN1+ReLU(t1) -> t2[4,128,...]
    conv3x3_kernel<256, 128, 8><<<dim3(16, 8, 4), 256>>>(
        t1, w2, b2, st1, g1w, g1b, t2);
    gn_stats_kernel<128, 4><<<16, 256>>>(t2, st2);

    // conv3: GN2+ReLU(t2) -> t3[4,64,...]
    conv3x3_kernel<128, 64, 4><<<dim3(16, 4, 4), 256>>>(
        t2, w3, b3, st2, g2w, g2b, t3);
    gn_stats_kernel<64, 4><<<16, 256>>>(t3, st3);

    // masked pooling over GN3+ReLU(t3)
    pool_kernel<<<dim3(16, 4), 256>>>(mk, g3w, g3b);

    // heads -> out (boxes 560 floats, then scores 80 floats)
    head_kernel<<<1, 640>>>(wb, bb, wc, bc, out);
}

// round 4
// speedup vs baseline: 2.6556x; 2.6556x over previous
#include <cuda_runtime.h>
#include <math.h>

#define HW 16384
#define BB 4
#define KK 20

// ---------------- scratch (device globals; no runtime allocation) ----------
__device__ float g_t1[4ll*256*128*128];   // conv1 raw output (pre-GN)  64 MB
__device__ float g_t2[4ll*128*128*128];   // conv2 raw output           32 MB
__device__ float g_t3[4ll*64*128*128];    // conv3 raw output           16 MB
__device__ float g_stats1[2*4*8];         // (mean, rstd) per (b, group)
__device__ float g_stats2[2*4*4];
__device__ float g_stats3[2*4*4];
__device__ float g_sums[4*20*64];
__device__ float g_cnts[4*20];

__device__ __forceinline__ unsigned f2tf32(float f) {
    unsigned r;
    asm("cvt.rna.tf32.f32 %0, %1;" : "=r"(r) : "f"(f));
    return r;
}

__device__ __forceinline__ void mma_tf32(float c[4],
                                         unsigned a0, unsigned a1, unsigned a2, unsigned a3,
                                         unsigned b0, unsigned b1) {
    asm volatile(
        "mma.sync.aligned.m16n8k8.row.col.f32.tf32.tf32.f32 "
        "{%0,%1,%2,%3}, {%4,%5,%6,%7}, {%8,%9}, {%0,%1,%2,%3};"
        : "+f"(c[0]), "+f"(c[1]), "+f"(c[2]), "+f"(c[3])
        : "r"(a0), "r"(a1), "r"(a2), "r"(a3), "r"(b0), "r"(b1));
}

// ---------------- zero accumulators ----------------------------------------
__global__ void zero_kernel() {
    int tid = threadIdx.x;
    for (int i = tid; i < 4*20*64; i += 256) g_sums[i] = 0.f;
    if (tid < 80) g_cnts[tid] = 0.f;
}

// ---------------- implicit-GEMM 3x3 conv via mma.sync tf32 -----------------
// Block 256 thr = 8 warps (4 M x 2 N). Block tile: 256 pixels (16x16) x 64 OC.
// Warp tile: 64 px x 32 OC = 4 M-frags x 4 N-frags (m16n8k8).
// K chunk = 8 input channels -> K = 72 = 9 exact k8 steps (no padding).
// GN+ReLU of the previous layer fused into the input staging.
template<int IC, int OC, int GROUPS_IN>
__global__ __launch_bounds__(256, 2)
void conv3x3_mma_kernel(const float* __restrict__ in,
                        const float* __restrict__ wgt,    // [OC][IC][3][3]
                        const float* __restrict__ bias,   // [OC]
                        const float* __restrict__ stats,  // [B*GROUPS_IN][2]
                        const float* __restrict__ gnw,
                        const float* __restrict__ gnb,
                        float* __restrict__ out)
{
    constexpr int ICC = 8;                       // input channels per chunk
    __shared__ unsigned s_in[ICC * 18 * 20];     // [icl][yy(18)][xx stride 20], tf32
    __shared__ unsigned s_w[72 * 73];            // [k(72)][oc stride 73], tf32

    const int tid  = threadIdx.x;
    const int wid  = tid >> 5;
    const int lane = tid & 31;
    const int lq   = lane & 3;      // quad col
    const int lr   = lane >> 2;     // quad row (0..7)
    const int warpM = wid & 3;      // 0..3
    const int warpN = wid >> 2;     // 0..1

    const int tileY = blockIdx.x >> 3, tileX = blockIdx.x & 7;
    const int y0 = tileY * 16, x0 = tileX * 16;
    const int ocBase = blockIdx.y * 64;
    const int b = blockIdx.z;

    float C[4][4][4];
#pragma unroll
    for (int f = 0; f < 4; f++)
#pragma unroll
        for (int g = 0; g < 4; g++)
#pragma unroll
            for (int i = 0; i < 4; i++) C[f][g][i] = 0.f;

#pragma unroll 1
    for (int ic0 = 0; ic0 < IC; ic0 += ICC) {
        // ---- stage input tile (18x18 halo per channel), fused GN+ReLU ----
        for (int idx = tid; idx < ICC * 18 * 18; idx += 256) {
            int icl = idx / 324;
            int rem = idx - icl * 324;
            int yy = rem / 18, xx = rem - yy * 18;
            int gy = y0 + yy - 1, gx = x0 + xx - 1;
            float v = 0.f;
            int c = ic0 + icl;
            if (gy >= 0 && gy < 128 && gx >= 0 && gx < 128) {
                v = in[(((size_t)b * IC + c) * HW) + gy * 128 + gx];
                if constexpr (GROUPS_IN > 0) {
                    int g = c / (IC / GROUPS_IN);
                    float m  = stats[(b * GROUPS_IN + g) * 2];
                    float rs = stats[(b * GROUPS_IN + g) * 2 + 1];
                    v = fmaxf(0.f, (v - m) * rs * gnw[c] + gnb[c]);
                }
            }
            s_in[icl * 360 + yy * 20 + xx] = f2tf32(v);
        }
        // ---- stage weights: s_w[k][oc], k = icl*9 + kappa (gmem-contig) ----
        for (int idx = tid; idx < 72 * 64; idx += 256) {
            int oc = idx / 72;
            int k  = idx - oc * 72;
            float v = wgt[(size_t)(ocBase + oc) * IC * 9 + ic0 * 9 + k];
            s_w[k * 73 + oc] = f2tf32(v);
        }
        __syncthreads();

#pragma unroll
        for (int step = 0; step < 9; step++) {
            // B fragments: 4 n-frags x 2 regs
            unsigned bf[4][2];
            const int kb0 = step * 8 + lq;
#pragma unroll
            for (int g = 0; g < 4; g++) {
                int ncol = warpN * 32 + g * 8 + lr;
                bf[g][0] = s_w[kb0 * 73 + ncol];
                bf[g][1] = s_w[(kb0 + 4) * 73 + ncol];
            }
            // A slot smem offsets: k -> (icl, ky, kx)
            const int k0 = step * 8 + lq;
            const int k1 = k0 + 4;
            const int icl0 = k0 / 9, kk0 = k0 - icl0 * 9;
            const int icl1 = k1 / 9, kk1 = k1 - icl1 * 9;
            const int off0 = icl0 * 360 + (kk0 / 3) * 20 + (kk0 % 3);
            const int off1 = icl1 * 360 + (kk1 / 3) * 20 + (kk1 % 3);

#pragma unroll
            for (int f = 0; f < 4; f++) {
                const int ymrow = (warpM * 4 + f) * 20;
                unsigned a0 = s_in[off0 + ymrow + lr];
                unsigned a1 = s_in[off0 + ymrow + lr + 8];
                unsigned a2 = s_in[off1 + ymrow + lr];
                unsigned a3 = s_in[off1 + ymrow + lr + 8];
#pragma unroll
                for (int g = 0; g < 4; g++)
                    mma_tf32(C[f][g], a0, a1, a2, a3, bf[g][0], bf[g][1]);
            }
        }
        __syncthreads();
    }

    // ---- epilogue: C[f][g] rows = pixel x (lr, lr+8), cols = oc (2lq, 2lq+1)
#pragma unroll
    for (int f = 0; f < 4; f++) {
        const int gy = y0 + warpM * 4 + f;
#pragma unroll
        for (int g = 0; g < 4; g++) {
            const int oc = ocBase + warpN * 32 + g * 8 + 2 * lq;
            const float bv0 = bias[oc], bv1 = bias[oc + 1];
            float* o0 = out + ((size_t)b * OC + oc) * HW + gy * 128 + x0;
            float* o1 = o0 + HW;
            o0[lr]     = C[f][g][0] + bv0;
            o1[lr]     = C[f][g][1] + bv1;
            o0[lr + 8] = C[f][g][2] + bv0;
            o1[lr + 8] = C[f][g][3] + bv1;
        }
    }
}

// ---------------- per-(b,group) mean/rstd ----------------------------------
template<int C, int G>
__global__ void gn_stats_kernel(const float* __restrict__ t, float* __restrict__ stats)
{
    constexpr int Cg = C / G;
    const int bg = blockIdx.x;                 // = b*G + g; slab is contiguous
    const size_t n = (size_t)Cg * HW;
    const float4* p = (const float4*)(t + (size_t)bg * n);
    const size_t n4 = n / 4;
    float s = 0.f, s2 = 0.f;
    for (size_t i = threadIdx.x; i < n4; i += blockDim.x) {
        float4 v = p[i];
        s  += v.x + v.y + v.z + v.w;
        s2 += v.x * v.x + v.y * v.y + v.z * v.z + v.w * v.w;
    }
    __shared__ float sh[2][8];
    for (int off = 16; off; off >>= 1) {
        s  += __shfl_down_sync(0xffffffffu, s,  off);
        s2 += __shfl_down_sync(0xffffffffu, s2, off);
    }
    int w = threadIdx.x >> 5, l = threadIdx.x & 31;
    if (l == 0) { sh[0][w] = s; sh[1][w] = s2; }
    __syncthreads();
    if (threadIdx.x == 0) {
        float S = 0.f, S2 = 0.f;
        for (int i = 0; i < 8; i++) { S += sh[0][i]; S2 += sh[1][i]; }
        float mean = S / (float)n;
        float var  = S2 / (float)n - mean * mean;
        stats[bg * 2]     = mean;
        stats[bg * 2 + 1] = rsqrtf(var + 1e-5f);
    }
}

// ---------------- masked segment-sum pooling (GN3+ReLU applied inline) -----
__global__ void pool_kernel(const int* __restrict__ masks,
                            const float* __restrict__ g3w,
                            const float* __restrict__ g3b)
{
    __shared__ float s_sum[20][64];
    __shared__ float s_cnt[20];
    const int tid = threadIdx.x;
    const int b = blockIdx.y;
    const int base = blockIdx.x * 1024;

    for (int i = tid; i < 20 * 64; i += 256) ((float*)s_sum)[i] = 0.f;
    if (tid < 20) s_cnt[tid] = 0.f;
    __syncthreads();

    const int* mp = masks + b * HW + base;
    for (int c = 0; c < 64; c++) {
        const int g = c >> 4;                       // 64 ch / 4 groups = 16
        const float m  = g_stats3[(b * 4 + g) * 2];
        const float rs = g_stats3[(b * 4 + g) * 2 + 1];
        const float gw = g3w[c], gb = g3b[c];
        const float* tp = g_t3 + ((size_t)b * 64 + c) * HW + base;
        for (int p = tid; p < 1024; p += 256) {
            int id = mp[p];
            if (id > 0) {
                float v = fmaxf(0.f, (tp[p] - m) * rs * gw + gb);
                atomicAdd(&s_sum[id - 1][c], v);
                if (c == 0) atomicAdd(&s_cnt[id - 1], 1.f);
            }
        }
    }
    __syncthreads();
    for (int i = tid; i < 20 * 64; i += 256) {
        int k = i >> 6, c = i & 63;
        atomicAdd(&g_sums[((size_t)b * 20 + k) * 64 + c], s_sum[k][c]);
    }
    if (tid < 20) atomicAdd(&g_cnts[b * 20 + tid], s_cnt[tid]);
}

// ---------------- heads: boxes [4,20,7] then scores [4,20] -----------------
__global__ void head_kernel(const float* __restrict__ wb, const float* __restrict__ bb,
                            const float* __restrict__ wc, const float* __restrict__ bc,
                            float* __restrict__ out)
{
    int t = threadIdx.x;
    if (t >= 640) return;
    int b = t / 160;
    int rem = t - b * 160;
    int k = rem >> 3, o = rem & 7;
    float inv = 1.f / (g_cnts[b * 20 + k] + 1e-6f);
    const float* sp = &g_sums[((size_t)b * 20 + k) * 64];
    if (o < 7) {
        float s = bb[o];
        for (int c = 0; c < 64; c++) s += sp[c] * inv * wb[o * 64 + c];
        out[(b * 20 + k) * 7 + o] = s;
    } else {
        float s = bc[0];
        for (int c = 0; c < 64; c++) s += sp[c] * inv * wc[c];
        out[560 + b * 20 + k] = 1.f / (1.f + expf(-s));
    }
}

// ---------------- launch ----------------------------------------------------
extern "C" void kernel_launch(void* const* d_in, const int* in_sizes, int n_in,
                              void* d_out, int out_size)
{
    const float* x   = (const float*)d_in[0];
    const int*   mk  = (const int*)  d_in[1];
    const float* w1  = (const float*)d_in[2];
    const float* b1  = (const float*)d_in[3];
    const float* g1w = (const float*)d_in[4];
    const float* g1b = (const float*)d_in[5];
    const float* w2  = (const float*)d_in[6];
    const float* b2  = (const float*)d_in[7];
    const float* g2w = (const float*)d_in[8];
    const float* g2b = (const float*)d_in[9];
    const float* w3  = (const float*)d_in[10];
    const float* b3  = (const float*)d_in[11];
    const float* g3w = (const float*)d_in[12];
    const float* g3b = (const float*)d_in[13];
    const float* wb  = (const float*)d_in[14];
    const float* bb  = (const float*)d_in[15];
    const float* wc  = (const float*)d_in[16];
    const float* bc  = (const float*)d_in[17];
    float* out = (float*)d_out;

    float *t1, *t2, *t3, *st1, *st2, *st3;
    cudaGetSymbolAddress((void**)&t1,  g_t1);
    cudaGetSymbolAddress((void**)&t2,  g_t2);
    cudaGetSymbolAddress((void**)&t3,  g_t3);
    cudaGetSymbolAddress((void**)&st1, g_stats1);
    cudaGetSymbolAddress((void**)&st2, g_stats2);
    cudaGetSymbolAddress((void**)&st3, g_stats3);

    zero_kernel<<<1, 256>>>();

    // conv1: x[4,512,128,128] -> t1[4,256,...]
    conv3x3_mma_kernel<512, 256, 0><<<dim3(64, 4, 4), 256>>>(
        x, w1, b1, nullptr, nullptr, nullptr, t1);
    gn_stats_kernel<256, 8><<<32, 256>>>(t1, st1);

    // conv2: GN1+ReLU(t1) -> t2[4,128,...]
    conv3x3_mma_kernel<256, 128, 8><<<dim3(64, 2, 4), 256>>>(
        t1, w2, b2, st1, g1w, g1b, t2);
    gn_stats_kernel<128, 4><<<16, 256>>>(t2, st2);

    // conv3: GN2+ReLU(t2) -> t3[4,64,...]
    conv3x3_mma_kernel<128, 64, 4><<<dim3(64, 1, 4), 256>>>(
        t2, w3, b3, st2, g2w, g2b, t3);
    gn_stats_kernel<64, 4><<<16, 256>>>(t3, st3);

    // masked pooling over GN3+ReLU(t3)
    pool_kernel<<<dim3(16, 4), 256>>>(mk, g3w, g3b);

    // heads -> out (boxes 560 floats, then scores 80 floats)
    head_kernel<<<1, 640>>>(wb, bb, wc, bc, out);
}

// round 9
// speedup vs baseline: 4.8908x; 1.8417x over previous
#include <cuda_runtime.h>
#include <math.h>
#include <stdint.h>

#define HW 16384
#define PR 132            // padded row stride (words)
#define PCH (130*132)     // padded per-channel words (17160)

// ---------------- scratch (device globals) ----------------------------------
__device__ float g_xp [4ll*512*PCH];   // x, tf32-rounded, zero-padded halo
__device__ float g_t1 [4ll*256*HW];    // conv1 raw out
__device__ float g_t1p[4ll*256*PCH];   // GN1+ReLU, rounded, padded
__device__ float g_t2 [4ll*128*HW];
__device__ float g_t2p[4ll*128*PCH];
__device__ float g_t3 [4ll*64*HW];
__device__ float g_t3t[4ll*HW*64];     // GN3+ReLU, channel-last
__device__ float g_w1t[256*512*9];     // weights: [ocG][chunk][72][64] tf32
__device__ float g_w2t[128*256*9];
__device__ float g_w3t[64*128*9];
__device__ float g_part1[4*8*2];       // (sum, sumsq) per (b, group)
__device__ float g_part2[4*4*2];
__device__ float g_part3[4*4*2];
__device__ float g_sums[4*20*64];
__device__ float g_cnts[4*20];

// ---------------- helpers ----------------------------------------------------
__device__ __forceinline__ unsigned f2tf32(float f) {
    unsigned r;
    asm("cvt.rna.tf32.f32 %0, %1;" : "=r"(r) : "f"(f));
    return r;
}
__device__ __forceinline__ void cpa16(uint32_t d, const float* s) {
    asm volatile("cp.async.ca.shared.global [%0], [%1], 16;" :: "r"(d), "l"(s));
}
__device__ __forceinline__ void cpa8(uint32_t d, const float* s) {
    asm volatile("cp.async.ca.shared.global [%0], [%1], 8;" :: "r"(d), "l"(s));
}
__device__ __forceinline__ void mma_tf32(float c[4],
                                         unsigned a0, unsigned a1, unsigned a2, unsigned a3,
                                         unsigned b0, unsigned b1) {
    asm volatile(
        "mma.sync.aligned.m16n8k8.row.col.f32.tf32.tf32.f32 "
        "{%0,%1,%2,%3}, {%4,%5,%6,%7}, {%8,%9}, {%0,%1,%2,%3};"
        : "+f"(c[0]), "+f"(c[1]), "+f"(c[2]), "+f"(c[3])
        : "r"(a0), "r"(a1), "r"(a2), "r"(a3), "r"(b0), "r"(b1));
}

// ---------------- zero accumulators -----------------------------------------
__global__ void zero_kernel() {
    int tid = threadIdx.x;
    for (int i = tid; i < 4*20*64; i += 256) g_sums[i] = 0.f;
    if (tid < 80) g_cnts[tid] = 0.f;
    if (tid < 64) g_part1[tid] = 0.f;
    if (tid < 32) { g_part2[tid] = 0.f; g_part3[tid] = 0.f; }
}

// ---------------- x -> rounded + padded -------------------------------------
__global__ void prep_x(const float* __restrict__ x) {
    int bc = blockIdx.x;                   // b*512 + c
    const float* src = x + (size_t)bc * HW;
    float* dst = g_xp + (size_t)bc * PCH;
    for (int i = threadIdx.x; i < PCH; i += 256) {
        int y = i / PR, xx = i - y * PR;
        float v = 0.f;
        if (y >= 1 && y <= 128 && xx >= 1 && xx <= 128)
            v = __uint_as_float(f2tf32(src[(y - 1) * 128 + xx - 1]));
        dst[i] = v;
    }
}

// ---------------- weights -> chunked [ocG][chunk][72][64], tf32 -------------
__global__ void prep_w(const float* __restrict__ w, float* __restrict__ dst,
                       int IC, int total) {
    int d = blockIdx.x * 256 + threadIdx.x;
    if (d >= total) return;
    int inner = d & 63;
    int t = d >> 6;
    int k = t % 72; t /= 72;
    int nch = IC >> 3;
    int chunk = t % nch;
    int ocG = t / nch;
    int oc = ocG * 64 + inner;
    int ic = chunk * 8 + k / 9;
    int kap = k % 9;
    dst[d] = __uint_as_float(f2tf32(w[((size_t)oc * IC + ic) * 9 + kap]));
}

// ---------------- implicit-GEMM conv: cp.async double-buffered --------------
// Block 256 thr = 8 warps (4M x 2N). Tile: 256 px (16x16) x 64 OC.
// K chunk = 8 input channels (K=72 = 9 x k8 steps). Input pre-rounded+padded.
// Epilogue: write raw out + per-(b,group) partial GN stats via atomics.
#define SMEM_WORDS (2*2880 + 2*4896)
template<int IC, int OC, int OCPG>
__global__ __launch_bounds__(256, 2)
void conv_mma(const float* __restrict__ inp,   // [b][c][PCH]
              const float* __restrict__ wt,    // [ocG][IC/8][4608]
              const float* __restrict__ bias,
              float* __restrict__ out,         // [b][oc][HW]
              float* __restrict__ part)        // [B*G][2]
{
    extern __shared__ float sm[];
    float* s_in = sm;                // 2 x 8x18x20
    float* s_w  = sm + 2 * 2880;     // 2 x 72x68

    const int tid = threadIdx.x, wid = tid >> 5, lane = tid & 31;
    const int lq = lane & 3, lr = lane >> 2;
    const int warpM = wid & 3, warpN = wid >> 2;
    const int tileY = blockIdx.x >> 3, tileX = blockIdx.x & 7;
    const int y0 = tileY * 16, x0 = tileX * 16;
    const int ocG = blockIdx.y;
    const int b = blockIdx.z;
    const float* inb = inp + (size_t)b * IC * PCH;
    const float* wbase = wt + (size_t)ocG * (IC / 8) * 4608;
    uint32_t s_in_b = (uint32_t)__cvta_generic_to_shared(s_in);
    uint32_t s_w_b  = (uint32_t)__cvta_generic_to_shared(s_w);

    float C[4][4][4] = {};

    const int NCH = IC / 8;
    auto stage = [&](int ch, int buf) {
        uint32_t sbase = s_in_b + buf * 2880 * 4;
        const float* gch = inb + (size_t)ch * 8 * PCH;
        for (int o = tid; o < 720; o += 256) {
            int row = o / 5, piece = o - row * 5;
            int icl = row / 18, yy = row - icl * 18;
            const float* src = gch + (size_t)icl * PCH + (y0 + yy) * PR + x0 + piece * 4;
            uint32_t dst = sbase + (icl * 360 + yy * 20 + piece * 4) * 4;
            if (piece < 4) cpa16(dst, src); else cpa8(dst, src);
        }
        uint32_t swb = s_w_b + buf * 4896 * 4;
        const float* wsrc = wbase + (size_t)ch * 4608;
        for (int j = tid; j < 1152; j += 256) {
            int k = j >> 4, col = (j & 15) * 4;
            cpa16(swb + (k * 68 + col) * 4, wsrc + j * 4);
        }
    };

    stage(0, 0);
    asm volatile("cp.async.commit_group;");
#pragma unroll 1
    for (int ch = 0; ch < NCH; ch++) {
        int cur = ch & 1;
        if (ch + 1 < NCH) stage(ch + 1, cur ^ 1);
        asm volatile("cp.async.commit_group;");
        asm volatile("cp.async.wait_group 1;");
        __syncthreads();
        const float* bi = s_in + cur * 2880;
        const float* bw = s_w + cur * 4896;
#pragma unroll
        for (int step = 0; step < 9; step++) {
            unsigned bf[4][2];
            const int kb0 = step * 8 + lq;
#pragma unroll
            for (int g = 0; g < 4; g++) {
                int ncol = warpN * 32 + g * 8 + lr;
                bf[g][0] = __float_as_uint(bw[kb0 * 68 + ncol]);
                bf[g][1] = __float_as_uint(bw[(kb0 + 4) * 68 + ncol]);
            }
            const int k0 = kb0, k1 = kb0 + 4;
            const int icl0 = k0 / 9, kk0 = k0 - icl0 * 9;
            const int icl1 = k1 / 9, kk1 = k1 - icl1 * 9;
            const int off0 = icl0 * 360 + (kk0 / 3) * 20 + (kk0 % 3);
            const int off1 = icl1 * 360 + (kk1 / 3) * 20 + (kk1 % 3);
#pragma unroll
            for (int f = 0; f < 4; f++) {
                const int ym = (warpM * 4 + f) * 20;
                unsigned a0 = __float_as_uint(bi[off0 + ym + lr]);
                unsigned a1 = __float_as_uint(bi[off0 + ym + lr + 8]);
                unsigned a2 = __float_as_uint(bi[off1 + ym + lr]);
                unsigned a3 = __float_as_uint(bi[off1 + ym + lr + 8]);
#pragma unroll
                for (int g = 0; g < 4; g++)
                    mma_tf32(C[f][g], a0, a1, a2, a3, bf[g][0], bf[g][1]);
            }
        }
        __syncthreads();
    }

    // ---- epilogue: store + partial GN stats ----
    constexpr int G = OC / OCPG;
    float s0 = 0.f, q0 = 0.f, s1 = 0.f, q1 = 0.f;
#pragma unroll
    for (int f = 0; f < 4; f++) {
        const int gy = y0 + warpM * 4 + f;
#pragma unroll
        for (int g = 0; g < 4; g++) {
            const int oc = ocG * 64 + warpN * 32 + g * 8 + 2 * lq;
            const float b0 = bias[oc], b1v = bias[oc + 1];
            float v0 = C[f][g][0] + b0, v1 = C[f][g][1] + b1v;
            float v2 = C[f][g][2] + b0, v3 = C[f][g][3] + b1v;
            float* o0 = out + ((size_t)b * OC + oc) * HW + gy * 128 + x0;
            o0[lr] = v0; o0[HW + lr] = v1; o0[lr + 8] = v2; o0[HW + lr + 8] = v3;
            if (OCPG == 16 && g >= 2) {
                s1 += v0 + v1 + v2 + v3;
                q1 += v0 * v0 + v1 * v1 + v2 * v2 + v3 * v3;
            } else {
                s0 += v0 + v1 + v2 + v3;
                q0 += v0 * v0 + v1 * v1 + v2 * v2 + v3 * v3;
            }
        }
    }
#pragma unroll
    for (int o = 16; o; o >>= 1) {
        s0 += __shfl_xor_sync(0xffffffffu, s0, o);
        q0 += __shfl_xor_sync(0xffffffffu, q0, o);
        if (OCPG == 16) {
            s1 += __shfl_xor_sync(0xffffffffu, s1, o);
            q1 += __shfl_xor_sync(0xffffffffu, q1, o);
        }
    }
    if (lane == 0) {
        int gidx = (ocG * 64 + warpN * 32) / OCPG;
        atomicAdd(&part[(b * G + gidx) * 2],     s0);
        atomicAdd(&part[(b * G + gidx) * 2 + 1], q0);
        if (OCPG == 16) {
            atomicAdd(&part[(b * G + gidx + 1) * 2],     s1);
            atomicAdd(&part[(b * G + gidx + 1) * 2 + 1], q1);
        }
    }
}

// ---------------- GN+ReLU apply -> rounded + padded (next conv input) -------
template<int C_, int G>
__global__ void gn_apply(const float* __restrict__ t, const float* __restrict__ part,
                         const float* __restrict__ gw, const float* __restrict__ gb,
                         float* __restrict__ outp)
{
    int bc = blockIdx.x;                   // b*C_ + c
    int b = bc / C_, c = bc - b * C_;
    int g = c / (C_ / G);
    float n = (float)(C_ / G) * (float)HW;
    float S = part[(b * G + g) * 2], S2 = part[(b * G + g) * 2 + 1];
    float mean = S / n;
    float rs = rsqrtf(S2 / n - mean * mean + 1e-5f);
    float sc = rs * gw[c];
    float sh = gb[c] - mean * sc;
    const float* src = t + (size_t)bc * HW;
    float* dst = outp + (size_t)bc * PCH;
    for (int i = threadIdx.x; i < PCH; i += 256) {
        int y = i / PR, xx = i - y * PR;
        float v = 0.f;
        if (y >= 1 && y <= 128 && xx >= 1 && xx <= 128)
            v = __uint_as_float(f2tf32(fmaxf(0.f, src[(y - 1) * 128 + xx - 1] * sc + sh)));
        dst[i] = v;
    }
}

// ---------------- GN3+ReLU apply + transpose to [b][p][64] ------------------
__global__ void gn_apply3t(const float* __restrict__ g3w, const float* __restrict__ g3b) {
    __shared__ float smT[64 * 65];
    int b = blockIdx.y;
    int p0 = blockIdx.x * 64;
    int tid = threadIdx.x;
#pragma unroll
    for (int i = 0; i < 16; i++) {
        int idx = tid + i * 256;
        int c = idx >> 6, pl = idx & 63;
        int g = c >> 4;
        float S = g_part3[(b * 4 + g) * 2], S2 = g_part3[(b * 4 + g) * 2 + 1];
        float n = 16.f * (float)HW;
        float mean = S / n;
        float rs = rsqrtf(S2 / n - mean * mean + 1e-5f);
        float sc = rs * g3w[c], sh = g3b[c] - mean * sc;
        smT[c * 65 + pl] = fmaxf(0.f, g_t3[((size_t)b * 64 + c) * HW + p0 + pl] * sc + sh);
    }
    __syncthreads();
    float* dst = g_t3t + ((size_t)b * HW + p0) * 64;
#pragma unroll
    for (int i = 0; i < 16; i++) {
        int idx = tid + i * 256;
        int pl = idx >> 6, c = idx & 63;
        dst[pl * 64 + c] = smT[c * 65 + pl];
    }
}

// ---------------- masked segment-sum pooling --------------------------------
__global__ void pool_kernel(const int* __restrict__ masks) {
    __shared__ float s_sum[20][64];
    __shared__ float s_cnt[20];
    const int tid = threadIdx.x;
    const int lane = tid & 31, w = tid >> 5;
    const int b = blockIdx.y;
    const int base = blockIdx.x * 1024;

    for (int i = tid; i < 20 * 64; i += 256) ((float*)s_sum)[i] = 0.f;
    if (tid < 20) s_cnt[tid] = 0.f;
    __syncthreads();

    const int* mp = masks + b * HW + base;
    for (int p = w; p < 1024; p += 8) {
        int id = mp[p];
        if (id > 0) {
            const float* hp = g_t3t + ((size_t)b * HW + base + p) * 64;
            atomicAdd(&s_sum[id - 1][lane],      hp[lane]);
            atomicAdd(&s_sum[id - 1][lane + 32], hp[lane + 32]);
            if (lane == 0) atomicAdd(&s_cnt[id - 1], 1.f);
        }
    }
    __syncthreads();
    for (int i = tid; i < 20 * 64; i += 256) {
        int k = i >> 6, c = i & 63;
        atomicAdd(&g_sums[((size_t)b * 20 + k) * 64 + c], s_sum[k][c]);
    }
    if (tid < 20) atomicAdd(&g_cnts[b * 20 + tid], s_cnt[tid]);
}

// ---------------- heads ------------------------------------------------------
__global__ void head_kernel(const float* __restrict__ wb, const float* __restrict__ bb,
                            const float* __restrict__ wc, const float* __restrict__ bc,
                            float* __restrict__ out)
{
    int t = threadIdx.x;
    if (t >= 640) return;
    int b = t / 160;
    int rem = t - b * 160;
    int k = rem >> 3, o = rem & 7;
    float inv = 1.f / (g_cnts[b * 20 + k] + 1e-6f);
    const float* sp = &g_sums[((size_t)b * 20 + k) * 64];
    if (o < 7) {
        float s = bb[o];
        for (int c = 0; c < 64; c++) s += sp[c] * inv * wb[o * 64 + c];
        out[(b * 20 + k) * 7 + o] = s;
    } else {
        float s = bc[0];
        for (int c = 0; c < 64; c++) s += sp[c] * inv * wc[c];
        out[560 + b * 20 + k] = 1.f / (1.f + expf(-s));
    }
}

// ---------------- launch ----------------------------------------------------
extern "C" void kernel_launch(void* const* d_in, const int* in_sizes, int n_in,
                              void* d_out, int out_size)
{
    const float* x   = (const float*)d_in[0];
    const int*   mk  = (const int*)  d_in[1];
    const float* w1  = (const float*)d_in[2];
    const float* b1  = (const float*)d_in[3];
    const float* g1w = (const float*)d_in[4];
    const float* g1b = (const float*)d_in[5];
    const float* w2  = (const float*)d_in[6];
    const float* b2  = (const float*)d_in[7];
    const float* g2w = (const float*)d_in[8];
    const float* g2b = (const float*)d_in[9];
    const float* w3  = (const float*)d_in[10];
    const float* b3  = (const float*)d_in[11];
    const float* g3w = (const float*)d_in[12];
    const float* g3b = (const float*)d_in[13];
    const float* wb  = (const float*)d_in[14];
    const float* bb  = (const float*)d_in[15];
    const float* wc  = (const float*)d_in[16];
    const float* bc  = (const float*)d_in[17];
    float* out = (float*)d_out;

    float *xp, *t1, *t1p, *t2, *t2p, *t3, *w1t, *w2t, *w3t, *p1, *p2, *p3;
    cudaGetSymbolAddress((void**)&xp,  g_xp);
    cudaGetSymbolAddress((void**)&t1,  g_t1);
    cudaGetSymbolAddress((void**)&t1p, g_t1p);
    cudaGetSymbolAddress((void**)&t2,  g_t2);
    cudaGetSymbolAddress((void**)&t2p, g_t2p);
    cudaGetSymbolAddress((void**)&t3,  g_t3);
    cudaGetSymbolAddress((void**)&w1t, g_w1t);
    cudaGetSymbolAddress((void**)&w2t, g_w2t);
    cudaGetSymbolAddress((void**)&w3t, g_w3t);
    cudaGetSymbolAddress((void**)&p1,  g_part1);
    cudaGetSymbolAddress((void**)&p2,  g_part2);
    cudaGetSymbolAddress((void**)&p3,  g_part3);

    const int SMEMB = SMEM_WORDS * 4;
    cudaFuncSetAttribute(conv_mma<512, 256, 32>, cudaFuncAttributeMaxDynamicSharedMemorySize, SMEMB);
    cudaFuncSetAttribute(conv_mma<256, 128, 32>, cudaFuncAttributeMaxDynamicSharedMemorySize, SMEMB);
    cudaFuncSetAttribute(conv_mma<128, 64, 16>,  cudaFuncAttributeMaxDynamicSharedMemorySize, SMEMB);

    zero_kernel<<<1, 256>>>();

    prep_x<<<4 * 512, 256>>>(x);
    prep_w<<<(256 * 512 * 9 + 255) / 256, 256>>>(w1, w1t, 512, 256 * 512 * 9);
    prep_w<<<(128 * 256 * 9 + 255) / 256, 256>>>(w2, w2t, 256, 128 * 256 * 9);
    prep_w<<<(64 * 128 * 9 + 255) / 256, 256>>>(w3, w3t, 128, 64 * 128 * 9);

    conv_mma<512, 256, 32><<<dim3(64, 4, 4), 256, SMEMB>>>(xp, w1t, b1, t1, p1);
    gn_apply<256, 8><<<4 * 256, 256>>>(t1, p1, g1w, g1b, t1p);

    conv_mma<256, 128, 32><<<dim3(64, 2, 4), 256, SMEMB>>>(t1p, w2t, b2, t2, p2);
    gn_apply<128, 4><<<4 * 128, 256>>>(t2, p2, g2w, g2b, t2p);

    conv_mma<128, 64, 16><<<dim3(64, 1, 4), 256, SMEMB>>>(t2p, w3t, b3, t3, p3);
    gn_apply3t<<<dim3(256, 4), 256>>>(g3w, g3b);

    pool_kernel<<<dim3(16, 4), 256>>>(mk);
    head_kernel<<<1, 640>>>(wb, bb, wc, bc, out);
}

// round 11
// speedup vs baseline: 9.5019x; 1.9428x over previous
#include <cuda_runtime.h>
#include <cuda_fp16.h>
#include <math.h>
#include <stdint.h>

#define HW 16384
#define PR 132            // padded row stride (words)
#define PCH (130*132)     // padded per-channel-pair words (17160)

// ---------------- scratch (device globals) ----------------------------------
__device__ __align__(16) unsigned g_xp [4ll*256*PCH];  // x, half2 ch-pairs, padded
__device__ float g_t1 [4ll*256*HW];                    // conv1 raw out (f32)
__device__ __align__(16) unsigned g_t1p[4ll*128*PCH];  // GN1+ReLU half2 pairs
__device__ float g_t2 [4ll*128*HW];
__device__ __align__(16) unsigned g_t2p[4ll*64*PCH];
__device__ float g_t3 [4ll*64*HW];
__device__ float g_t3t[4ll*HW*64];                     // GN3+ReLU, channel-last
__device__ __align__(16) unsigned g_w1t[256*512*9/2];  // [ocG][chunk][9][8][64] half2
__device__ __align__(16) unsigned g_w2t[128*256*9/2];
__device__ __align__(16) unsigned g_w3t[64*128*9/2];
__device__ float g_part1[4*8*2];                       // (sum, sumsq) per (b, group)
__device__ float g_part2[4*4*2];
__device__ float g_part3[4*4*2];
__device__ float g_sums[4*20*64];
__device__ float g_cnts[4*20];

// ---------------- helpers ----------------------------------------------------
__device__ __forceinline__ unsigned packh2(float a, float b) {
    __half2 h = __floats2half2_rn(a, b);
    return *(unsigned*)&h;
}
__device__ __forceinline__ void cpa16(uint32_t d, const void* s) {
    asm volatile("cp.async.ca.shared.global [%0], [%1], 16;" :: "r"(d), "l"(s));
}
__device__ __forceinline__ void cpa8(uint32_t d, const void* s) {
    asm volatile("cp.async.ca.shared.global [%0], [%1], 8;" :: "r"(d), "l"(s));
}
__device__ __forceinline__ void mma_f16(float c[4],
                                        unsigned a0, unsigned a1, unsigned a2, unsigned a3,
                                        unsigned b0, unsigned b1) {
    asm volatile(
        "mma.sync.aligned.m16n8k16.row.col.f32.f16.f16.f32 "
        "{%0,%1,%2,%3}, {%4,%5,%6,%7}, {%8,%9}, {%0,%1,%2,%3};"
        : "+f"(c[0]), "+f"(c[1]), "+f"(c[2]), "+f"(c[3])
        : "r"(a0), "r"(a1), "r"(a2), "r"(a3), "r"(b0), "r"(b1));
}

// ---------------- zero accumulators -----------------------------------------
__global__ void zero_kernel() {
    int tid = threadIdx.x;
    for (int i = tid; i < 4*20*64; i += 256) g_sums[i] = 0.f;
    if (tid < 80) g_cnts[tid] = 0.f;
    if (tid < 64) g_part1[tid] = 0.f;
    if (tid < 32) { g_part2[tid] = 0.f; g_part3[tid] = 0.f; }
}

// ---------------- x -> half2 channel pairs + padded halo --------------------
__global__ void prep_x(const float* __restrict__ x) {
    int p = blockIdx.x;                    // b*256 + cp
    int b = p >> 8, cp = p & 255;
    const float* s0 = x + ((size_t)b * 512 + 2 * cp) * HW;
    const float* s1 = s0 + HW;
    unsigned* dst = g_xp + (size_t)p * PCH;
    for (int i = threadIdx.x; i < PCH; i += 256) {
        int y = i / PR, xx = i - y * PR;
        unsigned v = 0u;
        if (y >= 1 && y <= 128 && xx >= 1 && xx <= 128) {
            int o = (y - 1) * 128 + xx - 1;
            v = packh2(s0[o], s1[o]);
        }
        dst[i] = v;
    }
}

// -------- weights -> [ocG][chunk16][kappa(9)][iclp(8)][oc(64)] half2 --------
__global__ void prep_w(const float* __restrict__ w, unsigned* __restrict__ dst,
                       int IC, int total) {
    int d = blockIdx.x * 256 + threadIdx.x;
    if (d >= total) return;
    int oc_in = d & 63;
    int t = d >> 6;
    int iclp = t & 7; t >>= 3;
    int kappa = t % 9; t /= 9;
    int nch = IC >> 4;
    int chunk = t % nch;
    int ocG = t / nch;
    int oc = ocG * 64 + oc_in;
    int ic = chunk * 16 + 2 * iclp;
    float v0 = w[((size_t)oc * IC + ic) * 9 + kappa];
    float v1 = w[((size_t)oc * IC + ic + 1) * 9 + kappa];
    dst[d] = packh2(v0, v1);
}

// ---------------- implicit-GEMM conv, fp16 m16n8k16, cp.async 2-buffer ------
// Block 256 thr = 8 warps (4M x 2N). Tile: 256 px (16x16) x 64 OC.
// K chunk = 16 input channels = 9 k16-steps (one 3x3 tap per step,
// k-within-step = channel; channel pairs packed as half2 planes).
#define SMEM_WORDS (2*2880 + 2*5184)
template<int IC, int OC, int OCPG>
__global__ __launch_bounds__(256, 2)
void conv_mma(const unsigned* __restrict__ inp,  // [b][icp][PCH] half2
              const unsigned* __restrict__ wt,   // [ocG][IC/16][4608] half2
              const float* __restrict__ bias,
              float* __restrict__ out,           // [b][oc][HW] f32
              float* __restrict__ part)          // [B*G][2]
{
    extern __shared__ unsigned sm[];
    unsigned* s_in = sm;                 // 2 x 8 planes x 18 x 20
    unsigned* s_w  = sm + 2 * 2880;      // 2 x 9 x 8 x 72

    const int tid = threadIdx.x, wid = tid >> 5, lane = tid & 31;
    const int lq = lane & 3, lr = lane >> 2;
    const int warpM = wid & 3, warpN = wid >> 2;
    const int tileY = blockIdx.x >> 3, tileX = blockIdx.x & 7;
    const int y0 = tileY * 16, x0 = tileX * 16;
    const int ocG = blockIdx.y;
    const int b = blockIdx.z;
    const unsigned* inb = inp + (size_t)b * (IC / 2) * PCH;
    const unsigned* wbase = wt + (size_t)ocG * (IC / 16) * 4608;
    uint32_t s_in_b = (uint32_t)__cvta_generic_to_shared(s_in);
    uint32_t s_w_b  = (uint32_t)__cvta_generic_to_shared(s_w);

    float C[4][4][4] = {};

    const int NCH = IC / 16;
    auto stage = [&](int ch, int buf) {
        uint32_t sbase = s_in_b + buf * 2880 * 4;
        const unsigned* gch = inb + (size_t)ch * 8 * PCH;
        for (int o = tid; o < 720; o += 256) {
            int row = o / 5, piece = o - row * 5;
            int iclp = row / 18, yy = row - iclp * 18;
            const unsigned* src = gch + (size_t)iclp * PCH + (y0 + yy) * PR + x0 + piece * 4;
            uint32_t dst = sbase + (iclp * 360 + yy * 20 + piece * 4) * 4;
            if (piece < 4) cpa16(dst, src); else cpa8(dst, src);
        }
        uint32_t swb = s_w_b + buf * 5184 * 4;
        const unsigned* wsrc = wbase + (size_t)ch * 4608;
        for (int j = tid; j < 1152; j += 256) {
            int r = j >> 4, c4 = (j & 15) * 4;
            cpa16(swb + (r * 72 + c4) * 4, wsrc + j * 4);
        }
    };

    stage(0, 0);
    asm volatile("cp.async.commit_group;");
#pragma unroll 1
    for (int ch = 0; ch < NCH; ch++) {
        int cur = ch & 1;
        if (ch + 1 < NCH) stage(ch + 1, cur ^ 1);
        asm volatile("cp.async.commit_group;");
        asm volatile("cp.async.wait_group 1;");
        __syncthreads();
        const unsigned* bi = s_in + cur * 2880;
        const unsigned* bw = s_w + cur * 5184;
#pragma unroll
        for (int kappa = 0; kappa < 9; kappa++) {
            unsigned bf[4][2];
#pragma unroll
            for (int g = 0; g < 4; g++) {
                int ncol = warpN * 32 + g * 8 + lr;
                bf[g][0] = bw[kappa * 576 + lq * 72 + ncol];
                bf[g][1] = bw[kappa * 576 + (lq + 4) * 72 + ncol];
            }
            const int ky = kappa / 3, kx = kappa % 3;
#pragma unroll
            for (int f = 0; f < 4; f++) {
                const int base = (warpM * 4 + f + ky) * 20 + kx;
                unsigned a0 = bi[lq * 360 + base + lr];
                unsigned a1 = bi[lq * 360 + base + lr + 8];
                unsigned a2 = bi[(lq + 4) * 360 + base + lr];
                unsigned a3 = bi[(lq + 4) * 360 + base + lr + 8];
#pragma unroll
                for (int g = 0; g < 4; g++)
                    mma_f16(C[f][g], a0, a1, a2, a3, bf[g][0], bf[g][1]);
            }
        }
        __syncthreads();
    }

    // ---- epilogue: store + partial GN stats ----
    constexpr int G = OC / OCPG;
    float s0 = 0.f, q0 = 0.f, s1 = 0.f, q1 = 0.f;
#pragma unroll
    for (int f = 0; f < 4; f++) {
        const int gy = y0 + warpM * 4 + f;
#pragma unroll
        for (int g = 0; g < 4; g++) {
            const int oc = ocG * 64 + warpN * 32 + g * 8 + 2 * lq;
            const float b0 = bias[oc], b1v = bias[oc + 1];
            float v0 = C[f][g][0] + b0, v1 = C[f][g][1] + b1v;
            float v2 = C[f][g][2] + b0, v3 = C[f][g][3] + b1v;
            float* o0 = out + ((size_t)b * OC + oc) * HW + gy * 128 + x0;
            o0[lr] = v0; o0[HW + lr] = v1; o0[lr + 8] = v2; o0[HW + lr + 8] = v3;
            if (OCPG == 16 && g >= 2) {
                s1 += v0 + v1 + v2 + v3;
                q1 += v0 * v0 + v1 * v1 + v2 * v2 + v3 * v3;
            } else {
                s0 += v0 + v1 + v2 + v3;
                q0 += v0 * v0 + v1 * v1 + v2 * v2 + v3 * v3;
            }
        }
    }
#pragma unroll
    for (int o = 16; o; o >>= 1) {
        s0 += __shfl_xor_sync(0xffffffffu, s0, o);
        q0 += __shfl_xor_sync(0xffffffffu, q0, o);
        if (OCPG == 16) {
            s1 += __shfl_xor_sync(0xffffffffu, s1, o);
            q1 += __shfl_xor_sync(0xffffffffu, q1, o);
        }
    }
    if (lane == 0) {
        int gidx = (ocG * 64 + warpN * 32) / OCPG;
        atomicAdd(&part[(b * G + gidx) * 2],     s0);
        atomicAdd(&part[(b * G + gidx) * 2 + 1], q0);
        if (OCPG == 16) {
            atomicAdd(&part[(b * G + gidx + 1) * 2],     s1);
            atomicAdd(&part[(b * G + gidx + 1) * 2 + 1], q1);
        }
    }
}

// ------- GN+ReLU apply -> half2 channel pairs, padded (next conv input) -----
template<int C_, int G>
__global__ void gn_apply(const float* __restrict__ t, const float* __restrict__ part,
                         const float* __restrict__ gw, const float* __restrict__ gb,
                         unsigned* __restrict__ outp)
{
    int p = blockIdx.x;                    // b*(C_/2) + cp
    int b = p / (C_ / 2), cp = p - b * (C_ / 2);
    int c0 = 2 * cp, c1 = c0 + 1;
    int g = c0 / (C_ / G);                 // pair always same group (group size >= 16)
    float n = (float)(C_ / G) * (float)HW;
    float S = part[(b * G + g) * 2], S2 = part[(b * G + g) * 2 + 1];
    float mean = S / n;
    float rs = rsqrtf(S2 / n - mean * mean + 1e-5f);
    float sc0 = rs * gw[c0], sh0 = gb[c0] - mean * sc0;
    float sc1 = rs * gw[c1], sh1 = gb[c1] - mean * sc1;
    const float* src0 = t + ((size_t)b * C_ + c0) * HW;
    const float* src1 = src0 + HW;
    unsigned* dst = outp + (size_t)p * PCH;
    for (int i = threadIdx.x; i < PCH; i += 256) {
        int y = i / PR, xx = i - y * PR;
        unsigned v = 0u;
        if (y >= 1 && y <= 128 && xx >= 1 && xx <= 128) {
            int o = (y - 1) * 128 + xx - 1;
            v = packh2(fmaxf(0.f, src0[o] * sc0 + sh0),
                       fmaxf(0.f, src1[o] * sc1 + sh1));
        }
        dst[i] = v;
    }
}

// ---------------- GN3+ReLU apply + transpose to [b][p][64] ------------------
__global__ void gn_apply3t(const float* __restrict__ g3w, const float* __restrict__ g3b) {
    __shared__ float smT[64 * 65];
    int b = blockIdx.y;
    int p0 = blockIdx.x * 64;
    int tid = threadIdx.x;
#pragma unroll
    for (int i = 0; i < 16; i++) {
        int idx = tid + i * 256;
        int c = idx >> 6, pl = idx & 63;
        int g = c >> 4;
        float S = g_part3[(b * 4 + g) * 2], S2 = g_part3[(b * 4 + g) * 2 + 1];
        float n = 16.f * (float)HW;
        float mean = S / n;
        float rs = rsqrtf(S2 / n - mean * mean + 1e-5f);
        float sc = rs * g3w[c], sh = g3b[c] - mean * sc;
        smT[c * 65 + pl] = fmaxf(0.f, g_t3[((size_t)b * 64 + c) * HW + p0 + pl] * sc + sh);
    }
    __syncthreads();
    float* dst = g_t3t + ((size_t)b * HW + p0) * 64;
#pragma unroll
    for (int i = 0; i < 16; i++) {
        int idx = tid + i * 256;
        int pl = idx >> 6, c = idx & 63;
        dst[pl * 64 + c] = smT[c * 65 + pl];
    }
}

// ---------------- masked segment-sum pooling --------------------------------
__global__ void pool_kernel(const int* __restrict__ masks) {
    __shared__ float s_sum[20][64];
    __shared__ float s_cnt[20];
    const int tid = threadIdx.x;
    const int lane = tid & 31, w = tid >> 5;
    const int b = blockIdx.y;
    const int base = blockIdx.x * 1024;

    for (int i = tid; i < 20 * 64; i += 256) ((float*)s_sum)[i] = 0.f;
    if (tid < 20) s_cnt[tid] = 0.f;
    __syncthreads();

    const int* mp = masks + b * HW + base;
    for (int p = w; p < 1024; p += 8) {
        int id = mp[p];
        if (id > 0) {
            const float* hp = g_t3t + ((size_t)b * HW + base + p) * 64;
            atomicAdd(&s_sum[id - 1][lane],      hp[lane]);
            atomicAdd(&s_sum[id - 1][lane + 32], hp[lane + 32]);
            if (lane == 0) atomicAdd(&s_cnt[id - 1], 1.f);
        }
    }
    __syncthreads();
    for (int i = tid; i < 20 * 64; i += 256) {
        int k = i >> 6, c = i & 63;
        atomicAdd(&g_sums[((size_t)b * 20 + k) * 64 + c], s_sum[k][c]);
    }
    if (tid < 20) atomicAdd(&g_cnts[b * 20 + tid], s_cnt[tid]);
}

// ---------------- heads ------------------------------------------------------
__global__ void head_kernel(const float* __restrict__ wb, const float* __restrict__ bb,
                            const float* __restrict__ wc, const float* __restrict__ bc,
                            float* __restrict__ out)
{
    int t = threadIdx.x;
    if (t >= 640) return;
    int b = t / 160;
    int rem = t - b * 160;
    int k = rem >> 3, o = rem & 7;
    float inv = 1.f / (g_cnts[b * 20 + k] + 1e-6f);
    const float* sp = &g_sums[((size_t)b * 20 + k) * 64];
    if (o < 7) {
        float s = bb[o];
        for (int c = 0; c < 64; c++) s += sp[c] * inv * wb[o * 64 + c];
        out[(b * 20 + k) * 7 + o] = s;
    } else {
        float s = bc[0];
        for (int c = 0; c < 64; c++) s += sp[c] * inv * wc[c];
        out[560 + b * 20 + k] = 1.f / (1.f + expf(-s));
    }
}

// ---------------- launch ----------------------------------------------------
extern "C" void kernel_launch(void* const* d_in, const int* in_sizes, int n_in,
                              void* d_out, int out_size)
{
    const float* x   = (const float*)d_in[0];
    const int*   mk  = (const int*)  d_in[1];
    const float* w1  = (const float*)d_in[2];
    const float* b1  = (const float*)d_in[3];
    const float* g1w = (const float*)d_in[4];
    const float* g1b = (const float*)d_in[5];
    const float* w2  = (const float*)d_in[6];
    const float* b2  = (const float*)d_in[7];
    const float* g2w = (const float*)d_in[8];
    const float* g2b = (const float*)d_in[9];
    const float* w3  = (const float*)d_in[10];
    const float* b3  = (const float*)d_in[11];
    const float* g3w = (const float*)d_in[12];
    const float* g3b = (const float*)d_in[13];
    const float* wb  = (const float*)d_in[14];
    const float* bb  = (const float*)d_in[15];
    const float* wc  = (const float*)d_in[16];
    const float* bc  = (const float*)d_in[17];
    float* out = (float*)d_out;

    unsigned *xp, *t1p, *t2p, *w1t, *w2t, *w3t;
    float *t1, *t2, *t3, *p1, *p2, *p3;
    cudaGetSymbolAddress((void**)&xp,  g_xp);
    cudaGetSymbolAddress((void**)&t1,  g_t1);
    cudaGetSymbolAddress((void**)&t1p, g_t1p);
    cudaGetSymbolAddress((void**)&t2,  g_t2);
    cudaGetSymbolAddress((void**)&t2p, g_t2p);
    cudaGetSymbolAddress((void**)&t3,  g_t3);
    cudaGetSymbolAddress((void**)&w1t, g_w1t);
    cudaGetSymbolAddress((void**)&w2t, g_w2t);
    cudaGetSymbolAddress((void**)&w3t, g_w3t);
    cudaGetSymbolAddress((void**)&p1,  g_part1);
    cudaGetSymbolAddress((void**)&p2,  g_part2);
    cudaGetSymbolAddress((void**)&p3,  g_part3);

    const int SMEMB = SMEM_WORDS * 4;
    cudaFuncSetAttribute(conv_mma<512, 256, 32>, cudaFuncAttributeMaxDynamicSharedMemorySize, SMEMB);
    cudaFuncSetAttribute(conv_mma<256, 128, 32>, cudaFuncAttributeMaxDynamicSharedMemorySize, SMEMB);
    cudaFuncSetAttribute(conv_mma<128, 64, 16>,  cudaFuncAttributeMaxDynamicSharedMemorySize, SMEMB);

    zero_kernel<<<1, 256>>>();

    prep_x<<<4 * 256, 256>>>(x);
    prep_w<<<(256 * 512 * 9 / 2 + 255) / 256, 256>>>(w1, w1t, 512, 256 * 512 * 9 / 2);
    prep_w<<<(128 * 256 * 9 / 2 + 255) / 256, 256>>>(w2, w2t, 256, 128 * 256 * 9 / 2);
    prep_w<<<(64 * 128 * 9 / 2 + 255) / 256, 256>>>(w3, w3t, 128, 64 * 128 * 9 / 2);

    conv_mma<512, 256, 32><<<dim3(64, 4, 4), 256, SMEMB>>>(xp, w1t, b1, t1, p1);
    gn_apply<256, 8><<<4 * 128, 256>>>(t1, p1, g1w, g1b, t1p);

    conv_mma<256, 128, 32><<<dim3(64, 2, 4), 256, SMEMB>>>(t1p, w2t, b2, t2, p2);
    gn_apply<128, 4><<<4 * 64, 256>>>(t2, p2, g2w, g2b, t2p);

    conv_mma<128, 64, 16><<<dim3(64, 1, 4), 256, SMEMB>>>(t2p, w3t, b3, t3, p3);
    gn_apply3t<<<dim3(256, 4), 256>>>(g3w, g3b);

    pool_kernel<<<dim3(16, 4), 256>>>(mk);
    head_kernel<<<1, 640>>>(wb, bb, wc, bc, out);
}